// round 11
// baseline (speedup 1.0000x reference)
#include <cuda_runtime.h>
#include <cuda_bf16.h>
#include <cstdint>

// ---------------------------------------------------------------------------
// out[32,1024] = concat_c( spatial_mean(feat_l) ) @ conv_w.T
// (bilinear half-pixel upsample at ratios 1,2,4,8 + mean == plain mean.)
// feat0 [32,256,56,56], feat1 [32,512,28,28], feat2 [32,1024,14,14],
// feat3 [32,2048,7,7], conv_w [1024,3840].
//
// SINGLE mixed-grid kernel (no streams/events — those break this harness's
// graph capture): blocks 0..147 are persistent GEMM blocks (exactly 1/SM),
// the rest are pool blocks. Resource budget (64 regs via launch_bounds,
// 43.5KB static smem) guarantees 1 GEMM + 3 pool blocks per SM, so the pool
// keeps running while GEMM blocks prefetch W (cp.async), spin on per-group
// counters, and compute groups as they are published. Pool ordered
// lvl3->lvl0 so GEMM's early items unlock first; lvl0 tail is tiny.
// ---------------------------------------------------------------------------

#define BATCH 32
#define CTOT  3840
#define EMB   1024

#define NGROUPS 60            // 64 channels per group (global c / 64)
#define GRP_EXPECT 2048       // 32 b * 64 c contributions per group

#define GBLKS  148            // persistent GEMM blocks (1 per SM)
#define NITEMS 960            // 16 e-tiles * 60 groups

// pool block counts, grid order lvl3, lvl2, lvl1, lvl0
#define NB3 2048
#define NB2 2048
#define NB1 1024
#define NB0 1024
#define POOL_BLKS (NB3 + NB2 + NB1 + NB0)
#define TOTAL_BLKS (GBLKS + POOL_BLKS)

__device__ float g_v[BATCH * CTOT];
__device__ int   g_cnt[NGROUPS];

__global__ void init_kernel() {
    if (threadIdx.x < NGROUPS) g_cnt[threadIdx.x] = 0;
}

__device__ __forceinline__ float warp_reduce(float s) {
    #pragma unroll
    for (int o = 16; o > 0; o >>= 1)
        s += __shfl_down_sync(0xFFFFFFFFu, s, o);
    return s;
}

__device__ __forceinline__ void ffma2(unsigned long long& d,
                                      unsigned long long a,
                                      unsigned long long b) {
    asm("fma.rn.f32x2 %0, %1, %2, %0;" : "+l"(d) : "l"(a), "l"(b));
}

// smem: ws double buffer 2 x [64e][68k] + vs [32b][68k]  (43,520 B < 48 KB)
#define WS_BUF_FLOATS (64 * 68)
#define VS_OFF        (2 * WS_BUF_FLOATS)

__global__ __launch_bounds__(256, 4)
void fused_kernel(const float* __restrict__ f0,
                  const float* __restrict__ f1,
                  const float* __restrict__ f2,
                  const float* __restrict__ f3,
                  const float* __restrict__ w,
                  float* __restrict__ out) {
    __shared__ float sm[2 * WS_BUF_FLOATS + 32 * 68];

    const int blk = blockIdx.x;
    const int tid = threadIdx.x;

    if (blk < GBLKS) {
        // =================== persistent GEMM block ===================
        float* vs = sm + VS_OFF;

        // prefetch W for first item
        {
            const int it = blk;
            const int gi = 59 - (it >> 4);
            const int e0 = (it & 15) << 6;
            const int k0 = gi << 6;
            #pragma unroll
            for (int r = 0; r < 4; r++) {
                const int cid = tid + r * 256;
                const int e   = cid >> 4;
                const int kc  = cid & 15;
                const float* src = w + (size_t)(e0 + e) * CTOT + k0 + kc * 4;
                unsigned dst = (unsigned)__cvta_generic_to_shared(&sm[e * 68 + kc * 4]);
                asm volatile("cp.async.cg.shared.global [%0], [%1], 16;\n"
                             :: "r"(dst), "l"(src));
            }
            asm volatile("cp.async.commit_group;\n");
        }

        int nbuf = 0;
        for (int it = blk; it < NITEMS; it += GBLKS) {
            const int nxt = it + GBLKS;
            const bool has_next = (nxt < NITEMS);

            // prefetch next item's W into the other buffer
            if (has_next) {
                const int gi2 = 59 - (nxt >> 4);
                const int e02 = (nxt & 15) << 6;
                const int k02 = gi2 << 6;
                const int base = (nbuf ^ 1) * WS_BUF_FLOATS;
                #pragma unroll
                for (int r = 0; r < 4; r++) {
                    const int cid = tid + r * 256;
                    const int e   = cid >> 4;
                    const int kc  = cid & 15;
                    const float* src = w + (size_t)(e02 + e) * CTOT + k02 + kc * 4;
                    unsigned dst = (unsigned)__cvta_generic_to_shared(&sm[base + e * 68 + kc * 4]);
                    asm volatile("cp.async.cg.shared.global [%0], [%1], 16;\n"
                                 :: "r"(dst), "l"(src));
                }
                asm volatile("cp.async.commit_group;\n");
            }

            const int gi = 59 - (it >> 4);
            const int e0 = (it & 15) << 6;
            const int k0 = gi << 6;

            // wait until this group's pooled channels are published
            if (tid == 0) {
                volatile int* c = &g_cnt[gi];
                while (*c < GRP_EXPECT) __nanosleep(64);
            }
            __syncthreads();
            __threadfence();

            // v slice [32b][64k] via L2: 2 f4 per thread
            #pragma unroll
            for (int r = 0; r < 2; r++) {
                const int i  = tid + r * 256;
                const int b  = i >> 4;
                const int kq = i & 15;
                float4 v4 = __ldcg((const float4*)&g_v[b * CTOT + k0 + kq * 4]);
                *(float4*)&vs[b * 68 + kq * 4] = v4;
            }

            if (has_next) asm volatile("cp.async.wait_group 1;\n" ::: "memory");
            else          asm volatile("cp.async.wait_group 0;\n" ::: "memory");
            __syncthreads();

            // compute: warp covers 8b x 32e; thread microtile 8b x 1e (f32x2 on K)
            const int lane = tid & 31;
            const int warp = tid >> 5;
            const int b0   = (warp & 3) * 8;
            const int ecol = ((warp >> 2) << 5) + lane;   // 0..63
            const float* wrow = &sm[nbuf * WS_BUF_FLOATS + ecol * 68];

            unsigned long long acc[8];
            #pragma unroll
            for (int i = 0; i < 8; i++) acc[i] = 0ull;

            #pragma unroll
            for (int k4 = 0; k4 < 16; k4++) {
                float4 wv = *(const float4*)&wrow[k4 * 4];
                const unsigned long long* wp = (const unsigned long long*)&wv;
                #pragma unroll
                for (int i = 0; i < 8; i++) {
                    float4 av = *(const float4*)&vs[(b0 + i) * 68 + k4 * 4];
                    const unsigned long long* ap = (const unsigned long long*)&av;
                    ffma2(acc[i], ap[0], wp[0]);
                    ffma2(acc[i], ap[1], wp[1]);
                }
            }

            #pragma unroll
            for (int i = 0; i < 8; i++) {
                float2 r2 = *(const float2*)&acc[i];
                atomicAdd(&out[(b0 + i) * EMB + e0 + ecol], r2.x + r2.y);
            }
            __syncthreads();   // protect vs/ws before next item overwrites
            nbuf ^= 1;
        }
        return;
    }

    // ======================= pool blocks =======================
    const int pblk = blk - GBLKS;
    const int lane = tid & 31;
    const int warp = tid >> 5;

    int gi, contrib;

    if (pblk < NB3) {
        // ---- level 3: 7x7 planes; warp handles 4 planes = 49 f4 ----
        const int l = pblk;
        const int g = l * 8 + warp;
        const float4* __restrict__ p = (const float4*)f3 + (size_t)g * 49;

        float a0 = 0.f, a1 = 0.f, a2 = 0.f, a3 = 0.f;
        #pragma unroll
        for (int rep = 0; rep < 2; rep++) {
            const int i = lane + rep * 32;
            if (i < 49) {
                float4 v = p[i];
                const int e = 4 * i;
                {
                    int pl = e / 49; float x = v.x;
                    if (pl == 0) a0 += x; else if (pl == 1) a1 += x;
                    else if (pl == 2) a2 += x; else a3 += x;
                }
                {
                    int pl = (e + 1) / 49; float x = v.y;
                    if (pl == 0) a0 += x; else if (pl == 1) a1 += x;
                    else if (pl == 2) a2 += x; else a3 += x;
                }
                {
                    int pl = (e + 2) / 49; float x = v.z;
                    if (pl == 0) a0 += x; else if (pl == 1) a1 += x;
                    else if (pl == 2) a2 += x; else a3 += x;
                }
                {
                    int pl = (e + 3) / 49; float x = v.w;
                    if (pl == 0) a0 += x; else if (pl == 1) a1 += x;
                    else if (pl == 2) a2 += x; else a3 += x;
                }
            }
        }
        a0 = warp_reduce(a0);
        a1 = warp_reduce(a1);
        a2 = warp_reduce(a2);
        a3 = warp_reduce(a3);
        if (lane == 0) {
            const int plane0 = g * 4;
            const int b = plane0 >> 11, c = plane0 & 2047;  // C=2048
            float* dst = &g_v[b * CTOT + 1792 + c];
            dst[0] = a0 * (1.f / 49.f);
            dst[1] = a1 * (1.f / 49.f);
            dst[2] = a2 * (1.f / 49.f);
            dst[3] = a3 * (1.f / 49.f);
        }
        gi = 28 + ((l & 63) >> 1);
        contrib = 32;
    } else if (pblk < NB3 + NB2) {
        // ---- level 2: 14x14 = 49 f4, 2 planes per warp ----
        const int l = pblk - NB3;
        const int plane0 = (l * 8 + warp) * 2;
        const float4* __restrict__ p = (const float4*)f2 + (size_t)plane0 * 49;
        float s0, s1;
        {
            float4 v0 = p[lane];
            float4 v1 = p[49 + lane];
            s0 = (v0.x + v0.y) + (v0.z + v0.w);
            s1 = (v1.x + v1.y) + (v1.z + v1.w);
        }
        if (lane < 17) {
            float4 v0 = p[32 + lane];
            float4 v1 = p[49 + 32 + lane];
            s0 += (v0.x + v0.y) + (v0.z + v0.w);
            s1 += (v1.x + v1.y) + (v1.z + v1.w);
        }
        s0 = warp_reduce(s0);
        s1 = warp_reduce(s1);
        if (lane == 0) {
            const int b = plane0 >> 10, c = plane0 & 1023;  // C=1024
            g_v[b * CTOT + 768 + c]     = s0 * (1.f / 196.f);
            g_v[b * CTOT + 768 + c + 1] = s1 * (1.f / 196.f);
        }
        gi = 12 + ((l & 63) >> 2);
        contrib = 16;
    } else if (pblk < NB3 + NB2 + NB1) {
        // ---- level 1: 28x28 = 196 f4, 2 planes per warp ----
        const int l = pblk - NB3 - NB2;
        const int plane0 = (l * 8 + warp) * 2;
        const float4* __restrict__ p = (const float4*)f1 + (size_t)plane0 * 196;
        float s0 = 0.f, s1 = 0.f;
        #pragma unroll
        for (int k = 0; k < 6; k++) {
            float4 v0 = p[lane + k * 32];
            float4 v1 = p[196 + lane + k * 32];
            s0 += (v0.x + v0.y) + (v0.z + v0.w);
            s1 += (v1.x + v1.y) + (v1.z + v1.w);
        }
        if (lane < 4) {
            float4 v0 = p[192 + lane];
            float4 v1 = p[196 + 192 + lane];
            s0 += (v0.x + v0.y) + (v0.z + v0.w);
            s1 += (v1.x + v1.y) + (v1.z + v1.w);
        }
        s0 = warp_reduce(s0);
        s1 = warp_reduce(s1);
        if (lane == 0) {
            const int b = plane0 >> 9, c = plane0 & 511;    // C=512
            g_v[b * CTOT + 256 + c]     = s0 * (1.f / 784.f);
            g_v[b * CTOT + 256 + c + 1] = s1 * (1.f / 784.f);
        }
        gi = 4 + ((l & 31) >> 2);
        contrib = 16;
    } else {
        // ---- level 0: 56x56 = 784 f4, 1 plane per warp ----
        const int l = pblk - NB3 - NB2 - NB1;
        const int plane = l * 8 + warp;
        const float4* __restrict__ p = (const float4*)f0 + (size_t)plane * 784;
        float a0 = 0.f, a1 = 0.f, a2 = 0.f, a3 = 0.f;
        #pragma unroll
        for (int k = 0; k < 6; k++) {
            float4 v0 = p[lane + (4 * k + 0) * 32];
            float4 v1 = p[lane + (4 * k + 1) * 32];
            float4 v2 = p[lane + (4 * k + 2) * 32];
            float4 v3 = p[lane + (4 * k + 3) * 32];
            a0 += (v0.x + v0.y) + (v0.z + v0.w);
            a1 += (v1.x + v1.y) + (v1.z + v1.w);
            a2 += (v2.x + v2.y) + (v2.z + v2.w);
            a3 += (v3.x + v3.y) + (v3.z + v3.w);
        }
        if (lane < 16) {
            float4 v = p[768 + lane];
            a0 += (v.x + v.y) + (v.z + v.w);
        }
        float s = warp_reduce((a0 + a1) + (a2 + a3));
        if (lane == 0) {
            const int b = plane >> 8, c = plane & 255;      // C=256
            g_v[b * CTOT + c] = s * (1.f / 3136.f);
        }
        gi = (l & 31) >> 3;
        contrib = 8;
    }

    // publish: per-thread fence, block barrier, single counter bump
    __threadfence();
    __syncthreads();
    if (tid == 0)
        atomicAdd(&g_cnt[gi], contrib);
}

// ---------------------------------------------------------------------------
extern "C" void kernel_launch(void* const* d_in, const int* in_sizes, int n_in,
                              void* d_out, int out_size) {
    const float* feat0  = (const float*)d_in[0];
    const float* feat1  = (const float*)d_in[1];
    const float* feat2  = (const float*)d_in[2];
    const float* feat3  = (const float*)d_in[3];
    const float* conv_w = (const float*)d_in[4];
    float* out = (float*)d_out;

    cudaMemsetAsync(d_out, 0, (size_t)out_size * sizeof(float), 0);
    init_kernel<<<1, 64>>>();

    fused_kernel<<<TOTAL_BLKS, 256>>>(feat0, feat1, feat2, feat3, conv_w, out);
}